// round 9
// baseline (speedup 1.0000x reference)
#include <cuda_runtime.h>
#include <cstdint>

#define B_ 4
#define S_ 2048
#define H_ 8
#define D_ 64
#define C_ 64
#define NC_ (S_/C_)      // 32
#define BH_ (B_*H_)      // 32
#define SCALE 0.125f
#define ST 68            // tile row stride (floats): 272B, 16B-aligned rows

// Per-(bh,chunk) 64x64 stateT scratch, stateT[e][d]: 16 MB
__device__ float g_state[(size_t)BH_*NC_*D_*D_];

__device__ __forceinline__ float featf(float x) {
    return x > 0.f ? x + 1.f : __expf(x);   // elu(x)+1
}
__device__ __forceinline__ uint32_t tf32r(float x) {
    uint32_t r; asm("cvt.rn.tf32.f32 %0, %1;" : "=r"(r) : "f"(x)); return r;
}
__device__ __forceinline__ uint32_t smem_u32(const void* p) {
    uint32_t a; asm("{ .reg .u64 t; cvta.to.shared.u64 t, %1; cvt.u32.u64 %0, t; }"
                    : "=r"(a) : "l"(p));
    return a;
}
__device__ __forceinline__ void cp16(uint32_t dst, const void* src) {
    asm volatile("cp.async.ca.shared.global [%0], [%1], 16;" :: "r"(dst), "l"(src));
}
#define CP_COMMIT() asm volatile("cp.async.commit_group;" ::: "memory")
#define CP_WAIT(n)  asm volatile("cp.async.wait_group %0;" :: "n"(n) : "memory")

#define MMA8(D, A0, A1, A2, A3, B0, B1)                                      \
    asm volatile("mma.sync.aligned.m16n8k8.row.col.f32.tf32.tf32.f32 "       \
        "{%0,%1,%2,%3}, {%4,%5,%6,%7}, {%8,%9}, {%0,%1,%2,%3};"              \
        : "+f"((D)[0]), "+f"((D)[1]), "+f"((D)[2]), "+f"((D)[3])             \
        : "r"(A0), "r"(A1), "r"(A2), "r"(A3), "r"(B0), "r"(B1))

#define LDM4(R0, R1, R2, R3, ADDR)                                           \
    asm volatile("ldmatrix.sync.aligned.m8n8.x4.shared.b16 {%0,%1,%2,%3}, [%4];" \
        : "=r"(R0), "=r"(R1), "=r"(R2), "=r"(R3) : "r"(ADDR))

// swizzled element offset (floats) within a [64][ST] tile
__device__ __forceinline__ uint32_t swz_off(int row, int col) {
    int g4 = (col >> 2) ^ ((row >> 2) & 7);
    return (uint32_t)(row * ST + g4 * 4 + (col & 3));
}
// per-lane ldmatrix fragment address; rl/cl precomputed from lane
__device__ __forceinline__ uint32_t frag_addr(uint32_t base, int row0, int col0,
                                              int rl, int cl) {
    int row = row0 + rl;
    int col = col0 + cl;
    int g4 = (col >> 2) ^ ((row >> 2) & 7);
    return base + (uint32_t)(row * ST + g4 * 4) * 4;
}

// ---------------------------------------------------------------------------
// Kernel 1: stateT[e][d] = sum_j v[j][e] * (k[j][d]*SCALE)
// A = vT[e][j], B = kT[d][j]; warp = (e-block 0..3, d-half 0..1).
// ---------------------------------------------------------------------------
__global__ void __launch_bounds__(256) k_chunk_sum(const float* __restrict__ qk,
                                                   const float* __restrict__ v) {
    extern __shared__ float sm[];
    float* vT = sm;                  // [64][ST] vT[e][j], swizzled, tf32 bits
    float* kT = vT + 64 * ST;        // [64][ST] kT[d][j], swizzled, tf32 bits
    const uint32_t vTb = smem_u32(vT);
    const uint32_t kTb = smem_u32(kT);

    const int t  = threadIdx.x;
    const int bh = blockIdx.x / NC_;
    const int c  = blockIdx.x % NC_;
    const int b  = bh / H_, h = bh % H_;
    const int s0 = c * C_;

    #pragma unroll
    for (int r = 0; r < 4; r++) {
        int idx = t + r * 256;
        int j   = idx >> 4;
        int d4  = (idx & 15) << 2;
        size_t s = (size_t)(s0 + j);
        const float4 kf = *reinterpret_cast<const float4*>(
            qk + ((((size_t)b * S_ + s) * 2 + 1) * H_ + h) * D_ + d4);
        kT[swz_off(d4 + 0, j)] = __uint_as_float(tf32r(featf(kf.x) * SCALE));
        kT[swz_off(d4 + 1, j)] = __uint_as_float(tf32r(featf(kf.y) * SCALE));
        kT[swz_off(d4 + 2, j)] = __uint_as_float(tf32r(featf(kf.z) * SCALE));
        kT[swz_off(d4 + 3, j)] = __uint_as_float(tf32r(featf(kf.w) * SCALE));
        const float4 vf = *reinterpret_cast<const float4*>(
            v + (((size_t)b * S_ + s) * H_ + h) * D_ + d4);
        vT[swz_off(d4 + 0, j)] = __uint_as_float(tf32r(vf.x));
        vT[swz_off(d4 + 1, j)] = __uint_as_float(tf32r(vf.y));
        vT[swz_off(d4 + 2, j)] = __uint_as_float(tf32r(vf.z));
        vT[swz_off(d4 + 3, j)] = __uint_as_float(tf32r(vf.w));
    }
    __syncthreads();

    const int warp = t >> 5, lane = t & 31;
    const int g = lane >> 2, tq = lane & 3;
    const int rl = (lane & 7) + ((lane >> 3) & 1) * 8;
    const int cl = (lane >> 4) * 4;
    const int eb = warp >> 1;        // e-block (m)
    const int dh = warp & 1;         // d-half (n)

    float acc[4][4];
    #pragma unroll
    for (int n = 0; n < 4; n++)
        #pragma unroll
        for (int p = 0; p < 4; p++) acc[n][p] = 0.f;

    #pragma unroll
    for (int jt = 0; jt < 8; jt++) {
        const int j0 = jt * 8;
        uint32_t a0, a1, a2, a3;
        LDM4(a0, a1, a2, a3, frag_addr(vTb, eb * 16, j0, rl, cl));
        #pragma unroll
        for (int pp = 0; pp < 2; pp++) {
            uint32_t b0, b1, b2, b3;
            LDM4(b0, b1, b2, b3, frag_addr(kTb, dh * 32 + pp * 16, j0, rl, cl));
            MMA8(acc[pp * 2 + 0], a0, a1, a2, a3, b0, b2);
            MMA8(acc[pp * 2 + 1], a0, a1, a2, a3, b1, b3);
        }
    }

    // direct fragment stores: stateT[e][d], float2 per (tile,row)
    float* base = g_state + (size_t)(bh * NC_ + c) * (D_ * D_);
    const int eA = eb * 16 + g, eB = eA + 8;
    #pragma unroll
    for (int m = 0; m < 4; m++) {
        const int d = dh * 32 + (m >> 1) * 16 + (m & 1) * 8 + 2 * tq;
        *reinterpret_cast<float2*>(base + eA * D_ + d) = make_float2(acc[m][0], acc[m][1]);
        *reinterpret_cast<float2*>(base + eB * D_ + d) = make_float2(acc[m][2], acc[m][3]);
    }
}

// ---------------------------------------------------------------------------
// Kernel 2: exclusive prefix over chunks; stores RN tf32-rounded bits.
// ---------------------------------------------------------------------------
__global__ void __launch_bounds__(256) k_prefix() {
    const int el  = blockIdx.x * 256 + threadIdx.x;   // float4 index
    const int bh  = el >> 10;
    const int off = (el & 1023) << 2;
    float* p = g_state + (size_t)bh * NC_ * (D_ * D_) + off;
    float4 run = make_float4(0.f, 0.f, 0.f, 0.f);
    #pragma unroll
    for (int c = 0; c < NC_; c++) {
        float4* q4 = reinterpret_cast<float4*>(p + (size_t)c * (D_ * D_));
        float4 tmp = *q4;
        float4 outq;
        outq.x = __uint_as_float(tf32r(run.x));
        outq.y = __uint_as_float(tf32r(run.y));
        outq.z = __uint_as_float(tf32r(run.z));
        outq.w = __uint_as_float(tf32r(run.w));
        *q4 = outq;
        run.x += tmp.x; run.y += tmp.y; run.z += tmp.z; run.w += tmp.w;
    }
}

// ---------------------------------------------------------------------------
// Kernel 3: out[i][e] = norm_i * ( q@stateT^T + causal(q@k^T) @ v )
// Tiles (swizzled): qS[i][d] | kS[j][d] | vT[e][j] | stT[e][d]
// sS[i][j] aliases stT; oS (plain) aliases qS.
// warp = (i-block ib 0..3, e-half eh 0..1). Score pairs: p in {eh, eh+2}.
// ---------------------------------------------------------------------------
__global__ void __launch_bounds__(256) k_output(const float* __restrict__ qk,
                                                const float* __restrict__ v,
                                                const float* __restrict__ nvec,
                                                const float* __restrict__ offset,
                                                float* __restrict__ out) {
    extern __shared__ float sm[];
    float* qS  = sm;
    float* kS  = qS + 64 * ST;
    float* vT  = kS + 64 * ST;
    float* stT = vT + 64 * ST;
    float* oS  = qS;                 // plain row-major staging after compute
    float* sS  = stT;                // scores alias state
    const uint32_t qSb  = smem_u32(qS);
    const uint32_t kSb  = smem_u32(kS);
    const uint32_t vTb  = smem_u32(vT);
    const uint32_t stTb = smem_u32(stT);

    const int t  = threadIdx.x;
    const int bh = blockIdx.x / NC_;
    const int c  = blockIdx.x % NC_;
    const int b  = bh / H_, h = bh % H_;
    const int s0 = c * C_;

    const float* stg = g_state + (size_t)(bh * NC_ + c) * (D_ * D_);

    // async stateT loads into swizzled granules (pre-rounded by k_prefix)
    #pragma unroll
    for (int r = 0; r < 4; r++) {
        int idx = t + r * 256;
        int row = idx >> 4;          // e
        int d4  = (idx & 15) << 2;
        uint32_t g4 = (uint32_t)((d4 >> 2) ^ ((row >> 2) & 7));
        cp16(stTb + (uint32_t)(row * ST + g4 * 4) * 4, stg + row * D_ + d4);
    }
    CP_COMMIT();

    // q, k (vectorized swizzled-granule stores), v (transpose scatter)
    #pragma unroll
    for (int r = 0; r < 4; r++) {
        int idx = t + r * 256;
        int row = idx >> 4;
        int d4  = (idx & 15) << 2;
        size_t s = (size_t)(s0 + row);
        const float4 qf = *reinterpret_cast<const float4*>(
            qk + ((((size_t)b * S_ + s) * 2 + 0) * H_ + h) * D_ + d4);
        uint4 qu = make_uint4(tf32r(featf(qf.x)), tf32r(featf(qf.y)),
                              tf32r(featf(qf.z)), tf32r(featf(qf.w)));
        *reinterpret_cast<uint4*>(qS + (row * ST + ((d4 >> 2) ^ ((row >> 2) & 7)) * 4)) = qu;
        const float4 kf = *reinterpret_cast<const float4*>(
            qk + ((((size_t)b * S_ + s) * 2 + 1) * H_ + h) * D_ + d4);
        uint4 ku = make_uint4(tf32r(featf(kf.x) * SCALE), tf32r(featf(kf.y) * SCALE),
                              tf32r(featf(kf.z) * SCALE), tf32r(featf(kf.w) * SCALE));
        *reinterpret_cast<uint4*>(kS + (row * ST + ((d4 >> 2) ^ ((row >> 2) & 7)) * 4)) = ku;
        const float4 vf = *reinterpret_cast<const float4*>(
            v + (((size_t)b * S_ + s) * H_ + h) * D_ + d4);
        vT[swz_off(d4 + 0, row)] = __uint_as_float(tf32r(vf.x));
        vT[swz_off(d4 + 1, row)] = __uint_as_float(tf32r(vf.y));
        vT[swz_off(d4 + 2, row)] = __uint_as_float(tf32r(vf.z));
        vT[swz_off(d4 + 3, row)] = __uint_as_float(tf32r(vf.w));
    }

    const int warp = t >> 5, lane = t & 31;
    const int g = lane >> 2, tq = lane & 3;
    const int rl = (lane & 7) + ((lane >> 3) & 1) * 8;
    const int cl = (lane >> 4) * 4;
    const int ib = warp >> 1;
    const int eh = warp & 1;
    const int i0 = ib * 16;
    const int ntS = 2 * ib + 2;      // causal j-tiles for this i-block
    const int pmax = ib + 1;         // active score pairs: p < pmax

    const float offh = offset[h];
    const int iA = i0 + g, iB = iA + 8;
    float zA = nvec[((size_t)b * S_ + s0 + iA) * H_ + h] + offh;
    float zB = nvec[((size_t)b * S_ + s0 + iB) * H_ + h] + offh;

    CP_WAIT(0);
    __syncthreads();

    float dO[4][4];
    float dS[4][4];                  // [pair-slot][tile] flattened
    #pragma unroll
    for (int n = 0; n < 4; n++)
        #pragma unroll
        for (int p = 0; p < 4; p++) { dO[n][p] = 0.f; dS[n][p] = 0.f; }

    // Phase 1: out1 = q @ stateT^T ; scores = q @ k^T (assigned pairs)
    #pragma unroll
    for (int kt = 0; kt < 8; kt++) {
        const int d0 = kt * 8;
        uint32_t a0, a1, a2, a3;
        LDM4(a0, a1, a2, a3, frag_addr(qSb, i0, d0, rl, cl));
        #pragma unroll
        for (int pp = 0; pp < 2; pp++) {
            uint32_t b0, b1, b2, b3;
            LDM4(b0, b1, b2, b3, frag_addr(stTb, eh * 32 + pp * 16, d0, rl, cl));
            MMA8(dO[pp * 2 + 0], a0, a1, a2, a3, b0, b2);
            MMA8(dO[pp * 2 + 1], a0, a1, a2, a3, b1, b3);
        }
        #pragma unroll
        for (int pi = 0; pi < 2; pi++) {
            const int p = eh + 2 * pi;
            if (p >= pmax) break;
            uint32_t b0, b1, b2, b3;
            LDM4(b0, b1, b2, b3, frag_addr(kSb, p * 16, d0, rl, cl));
            MMA8(dS[pi * 2 + 0], a0, a1, a2, a3, b0, b2);
            MMA8(dS[pi * 2 + 1], a0, a1, a2, a3, b1, b3);
        }
    }

    __syncthreads();           // stT reads done; sS may overwrite

    // Causal mask + store score tiles (swizzled scalar stores)
    #pragma unroll
    for (int pi = 0; pi < 2; pi++) {
        const int p = eh + 2 * pi;
        if (p >= pmax) break;
        #pragma unroll
        for (int tt = 0; tt < 2; tt++) {
            const int jt = 2 * p + tt;
            const int j = jt * 8 + 2 * tq;
            const float* dd = dS[pi * 2 + tt];
            sS[swz_off(iA, j)]     = __uint_as_float(tf32r((j     <= iA) ? dd[0] : 0.f));
            sS[swz_off(iA, j + 1)] = __uint_as_float(tf32r((j + 1 <= iA) ? dd[1] : 0.f));
            sS[swz_off(iB, j)]     = __uint_as_float(tf32r((j     <= iB) ? dd[2] : 0.f));
            sS[swz_off(iB, j + 1)] = __uint_as_float(tf32r((j + 1 <= iB) ? dd[3] : 0.f));
        }
    }
    __syncthreads();           // scores visible to all

    // Phase 2: out += scores @ v  (A = sS, B = vT)
    #pragma unroll
    for (int kt = 0; kt < 8; kt++) {
        if (kt >= ntS) break;
        const int j0 = kt * 8;
        uint32_t a0, a1, a2, a3;
        LDM4(a0, a1, a2, a3, frag_addr(stTb, i0, j0, rl, cl));   // sS == stT
        #pragma unroll
        for (int pp = 0; pp < 2; pp++) {
            uint32_t b0, b1, b2, b3;
            LDM4(b0, b1, b2, b3, frag_addr(vTb, eh * 32 + pp * 16, j0, rl, cl));
            MMA8(dO[pp * 2 + 0], a0, a1, a2, a3, b0, b2);
            MMA8(dO[pp * 2 + 1], a0, a1, a2, a3, b1, b3);
        }
    }

    // Epilogue: norm scale, stage into oS (plain layout, aliases qS)
    float nA = 1.f / (1.f + __expf(zA));
    float nB = 1.f / (1.f + __expf(zB));
    #pragma unroll
    for (int m = 0; m < 4; m++) {
        const int e = eh * 32 + (m >> 1) * 16 + (m & 1) * 8 + 2 * tq;
        oS[iA * ST + e]     = dO[m][0] * nA;
        oS[iA * ST + e + 1] = dO[m][1] * nA;
        oS[iB * ST + e]     = dO[m][2] * nB;
        oS[iB * ST + e + 1] = dO[m][3] * nB;
    }
    __syncthreads();

    #pragma unroll
    for (int r = 0; r < 4; r++) {
        int idx = t + r * 256;
        int row = idx >> 4;
        int d4  = (idx & 15) << 2;
        float* op = out + (((size_t)b * S_ + s0 + row) * H_ + h) * D_ + d4;
        *reinterpret_cast<float4*>(op) = *reinterpret_cast<const float4*>(&oS[row * ST + d4]);
    }
}

// ---------------------------------------------------------------------------
extern "C" void kernel_launch(void* const* d_in, const int* in_sizes, int n_in,
                              void* d_out, int out_size) {
    (void)in_sizes; (void)n_in; (void)out_size;
    const float* qk     = (const float*)d_in[0];
    const float* v      = (const float*)d_in[1];
    const float* nvec   = (const float*)d_in[2];
    const float* offset = (const float*)d_in[3];
    float* out = (float*)d_out;

    const int smem1 = (2 * 64 * ST) * (int)sizeof(float);   // 34816
    const int smem3 = (4 * 64 * ST) * (int)sizeof(float);   // 69632
    cudaFuncSetAttribute(k_chunk_sum, cudaFuncAttributeMaxDynamicSharedMemorySize, smem1);
    cudaFuncSetAttribute(k_output,    cudaFuncAttributeMaxDynamicSharedMemorySize, smem3);

    k_chunk_sum<<<BH_ * NC_, 256, smem1>>>(qk, v);
    k_prefix<<<128, 256>>>();
    k_output<<<BH_ * NC_, 256, smem3>>>(qk, v, nvec, offset, out);
}

// round 10
// speedup vs baseline: 1.0392x; 1.0392x over previous
#include <cuda_runtime.h>
#include <cstdint>

#define B_ 4
#define S_ 2048
#define H_ 8
#define D_ 64
#define C_ 64
#define NC_ (S_/C_)      // 32
#define BH_ (B_*H_)      // 32
#define SCALE 0.125f

// Per-(bh,chunk) 64x64 state scratch, state[d][e]: 16 MB
__device__ float g_state[(size_t)BH_*NC_*D_*D_];

__device__ __forceinline__ float featf(float x) {
    return x > 0.f ? x + 1.f : __expf(x);   // elu(x)+1
}
__device__ __forceinline__ uint32_t tf32r(float x) {
    uint32_t r; asm("cvt.rn.tf32.f32 %0, %1;" : "=r"(r) : "f"(x)); return r;
}
__device__ __forceinline__ uint32_t smem_u32(const void* p) {
    uint32_t a; asm("{ .reg .u64 t; cvta.to.shared.u64 t, %1; cvt.u32.u64 %0, t; }"
                    : "=r"(a) : "l"(p));
    return a;
}
__device__ __forceinline__ void cp16(uint32_t dst, const void* src) {
    asm volatile("cp.async.ca.shared.global [%0], [%1], 16;" :: "r"(dst), "l"(src));
}
#define CP_COMMIT() asm volatile("cp.async.commit_group;" ::: "memory")
#define CP_WAIT(n)  asm volatile("cp.async.wait_group %0;" :: "n"(n) : "memory")

// D(16x8,f32) += A(16x8,tf32) @ B(8x8,tf32)   [m16n8k8 row.col]
#define MMA8(D, A0, A1, A2, A3, B0, B1)                                      \
    asm volatile("mma.sync.aligned.m16n8k8.row.col.f32.tf32.tf32.f32 "       \
        "{%0,%1,%2,%3}, {%4,%5,%6,%7}, {%8,%9}, {%0,%1,%2,%3};"              \
        : "+f"((D)[0]), "+f"((D)[1]), "+f"((D)[2]), "+f"((D)[3])             \
        : "r"(A0), "r"(A1), "r"(A2), "r"(A3), "r"(B0), "r"(B1))

// ---------------------------------------------------------------------------
// Kernel 1: state[d][e] = sum_j (k[j][d]*SCALE) * v[j][e]
// 256 threads = 8 warps: warp = (d-block 0..3, e-half 0..1).
// All tiles via cp.async; k transformed smem->smem with conflict-free mapping.
// ---------------------------------------------------------------------------
__global__ void __launch_bounds__(256) k_chunk_sum(const float* __restrict__ qk,
                                                   const float* __restrict__ v) {
    extern __shared__ float sm[];
    float* kst = sm;                 // [64][68] raw k[j][d] staging
    float* kT  = kst + 64 * 68;      // [64][65] kT[d][j] (tf32 bits)
    float* vS  = kT + 64 * 65;       // [64][68] v[j][e]  (raw f32)
    uint32_t* kTu = reinterpret_cast<uint32_t*>(kT);
    const uint32_t kstb = smem_u32(kst);
    const uint32_t vSb  = smem_u32(vS);

    const int t  = threadIdx.x;
    const int bh = blockIdx.x / NC_;
    const int c  = blockIdx.x % NC_;
    const int b  = bh / H_, h = bh % H_;
    const int s0 = c * C_;

    #pragma unroll
    for (int r = 0; r < 4; r++) {
        int idx = t + r * 256;
        int j   = idx >> 4;
        int d4  = (idx & 15) << 2;
        size_t s = (size_t)(s0 + j);
        cp16(kstb + (uint32_t)(j * 68 + d4) * 4,
             qk + ((((size_t)b * S_ + s) * 2 + 1) * H_ + h) * D_ + d4);
        cp16(vSb + (uint32_t)(j * 68 + d4) * 4,
             v + (((size_t)b * S_ + s) * H_ + h) * D_ + d4);
    }
    CP_COMMIT();
    CP_WAIT(0);
    __syncthreads();

    // transform k: lane j consecutive -> LDS.128 and STS both conflict-free
    {
        const int j  = t & 63;
        const int d0 = (t >> 6) << 4;
        #pragma unroll
        for (int i = 0; i < 4; i++) {
            const float4 kf = *reinterpret_cast<const float4*>(&kst[j * 68 + d0 + i * 4]);
            kTu[(d0 + i * 4 + 0) * 65 + j] = tf32r(featf(kf.x) * SCALE);
            kTu[(d0 + i * 4 + 1) * 65 + j] = tf32r(featf(kf.y) * SCALE);
            kTu[(d0 + i * 4 + 2) * 65 + j] = tf32r(featf(kf.z) * SCALE);
            kTu[(d0 + i * 4 + 3) * 65 + j] = tf32r(featf(kf.w) * SCALE);
        }
    }
    __syncthreads();

    const int warp = t >> 5, lane = t & 31;
    const int g = lane >> 2, tq = lane & 3;
    const int d0w = (warp >> 1) * 16;
    const int eh  = warp & 1;

    float acc[4][4];
    #pragma unroll
    for (int n = 0; n < 4; n++)
        #pragma unroll
        for (int p = 0; p < 4; p++) acc[n][p] = 0.f;

    #pragma unroll
    for (int kt = 0; kt < 8; kt++) {
        const int j0 = kt * 8;
        uint32_t a0 = kTu[(d0w + g)     * 65 + j0 + tq];
        uint32_t a1 = kTu[(d0w + g + 8) * 65 + j0 + tq];
        uint32_t a2 = kTu[(d0w + g)     * 65 + j0 + tq + 4];
        uint32_t a3 = kTu[(d0w + g + 8) * 65 + j0 + tq + 4];
        #pragma unroll
        for (int nt = 0; nt < 4; nt++) {
            const int e0 = (eh * 4 + nt) * 8;
            uint32_t b0 = tf32r(vS[(j0 + tq)     * 68 + e0 + g]);
            uint32_t b1 = tf32r(vS[(j0 + tq + 4) * 68 + e0 + g]);
            MMA8(acc[nt], a0, a1, a2, a3, b0, b1);
        }
    }

    // direct fragment stores: each warp-op = 8 fully-used 32B sectors
    float* base = g_state + (size_t)(bh * NC_ + c) * (D_ * D_);
    #pragma unroll
    for (int nt = 0; nt < 4; nt++) {
        const int e = (eh * 4 + nt) * 8 + 2 * tq;
        *reinterpret_cast<float2*>(base + (d0w + g)     * D_ + e) =
            make_float2(acc[nt][0], acc[nt][1]);
        *reinterpret_cast<float2*>(base + (d0w + g + 8) * D_ + e) =
            make_float2(acc[nt][2], acc[nt][3]);
    }
}

// ---------------------------------------------------------------------------
// Kernel 2: exclusive prefix over chunks (float4/thread).
// Accumulates in f32; STORES RN tf32-rounded bits (k3 reads bits directly).
// ---------------------------------------------------------------------------
__global__ void __launch_bounds__(256) k_prefix() {
    const int el  = blockIdx.x * 256 + threadIdx.x;   // float4 index
    const int bh  = el >> 10;
    const int off = (el & 1023) << 2;
    float* p = g_state + (size_t)bh * NC_ * (D_ * D_) + off;
    float4 run = make_float4(0.f, 0.f, 0.f, 0.f);
    #pragma unroll
    for (int c = 0; c < NC_; c++) {
        float4* q4 = reinterpret_cast<float4*>(p + (size_t)c * (D_ * D_));
        float4 tmp = *q4;
        float4 outq;
        outq.x = __uint_as_float(tf32r(run.x));
        outq.y = __uint_as_float(tf32r(run.y));
        outq.z = __uint_as_float(tf32r(run.z));
        outq.w = __uint_as_float(tf32r(run.w));
        *q4 = outq;
        run.x += tmp.x; run.y += tmp.y; run.z += tmp.z; run.w += tmp.w;
    }
}

// ---------------------------------------------------------------------------
// Kernel 3: out[i][e] = norm_i * ( q@state + causal(q@k^T) @ v )
// 256 threads = 8 warps: warp = (i-block ib 0..3, e-half eh 0..1).
// smem: qS | kS | vS | stS (each [64][68]); sS aliases stS; oS aliases qS.
// state arrives pre-rounded (bits) from k_prefix; v rounded inline.
// ---------------------------------------------------------------------------
__global__ void __launch_bounds__(256) k_output(const float* __restrict__ qk,
                                                const float* __restrict__ v,
                                                const float* __restrict__ nvec,
                                                const float* __restrict__ offset,
                                                float* __restrict__ out) {
    extern __shared__ float sm[];
    float* qS  = sm;                 // q (tf32 bits); later out staging
    float* kS  = qS + 64 * 68;
    float* vS  = kS + 64 * 68;       // raw f32
    float* stS = vS + 64 * 68;       // tf32 bits; later scores [64][65]
    float* oS  = qS;
    float* sS  = stS;
    uint32_t* qSu  = reinterpret_cast<uint32_t*>(qS);
    uint32_t* kSu  = reinterpret_cast<uint32_t*>(kS);
    uint32_t* stSu = reinterpret_cast<uint32_t*>(stS);
    uint32_t* sSu  = reinterpret_cast<uint32_t*>(sS);
    const uint32_t smb = smem_u32(sm);

    const int t  = threadIdx.x;
    const int bh = blockIdx.x / NC_;
    const int c  = blockIdx.x % NC_;
    const int b  = bh / H_, h = bh % H_;
    const int s0 = c * C_;

    const float* stg = g_state + (size_t)(bh * NC_ + c) * (D_ * D_);

    // group 0: state; group 1: v
    #pragma unroll
    for (int r = 0; r < 4; r++) {
        int idx = t + r * 256;
        int row = idx >> 4;
        int d4  = (idx & 15) << 2;
        cp16(smb + (uint32_t)(3 * 64 * 68 + row * 68 + d4) * 4, stg + row * D_ + d4);
    }
    CP_COMMIT();
    #pragma unroll
    for (int r = 0; r < 4; r++) {
        int idx = t + r * 256;
        int row = idx >> 4;
        int d4  = (idx & 15) << 2;
        cp16(smb + (uint32_t)(2 * 64 * 68 + row * 68 + d4) * 4,
             v + (((size_t)b * S_ + s0 + row) * H_ + h) * D_ + d4);
    }
    CP_COMMIT();

    // q,k: batch ALL global loads first (MLP=8), then transform+store
    float4 qf[4], kf[4];
    #pragma unroll
    for (int r = 0; r < 4; r++) {
        int idx = t + r * 256;
        int row = idx >> 4;
        int d4  = (idx & 15) << 2;
        size_t s = (size_t)(s0 + row);
        qf[r] = *reinterpret_cast<const float4*>(
            qk + ((((size_t)b * S_ + s) * 2 + 0) * H_ + h) * D_ + d4);
        kf[r] = *reinterpret_cast<const float4*>(
            qk + ((((size_t)b * S_ + s) * 2 + 1) * H_ + h) * D_ + d4);
    }
    #pragma unroll
    for (int r = 0; r < 4; r++) {
        int idx = t + r * 256;
        int row = idx >> 4;
        int d4  = (idx & 15) << 2;
        uint4 qu = make_uint4(tf32r(featf(qf[r].x)), tf32r(featf(qf[r].y)),
                              tf32r(featf(qf[r].z)), tf32r(featf(qf[r].w)));
        *reinterpret_cast<uint4*>(&qSu[row * 68 + d4]) = qu;
        uint4 ku = make_uint4(tf32r(featf(kf[r].x) * SCALE), tf32r(featf(kf[r].y) * SCALE),
                              tf32r(featf(kf[r].z) * SCALE), tf32r(featf(kf[r].w) * SCALE));
        *reinterpret_cast<uint4*>(&kSu[row * 68 + d4]) = ku;
    }

    const int warp = t >> 5, lane = t & 31;
    const int g = lane >> 2, tq = lane & 3;
    const int ib = warp >> 1;
    const int eh = warp & 1;
    const int i0 = ib * 16;
    const int ntS = 2 * ib + 2;      // causal j-tiles for this i-block

    const float offh = offset[h];
    const int iA = i0 + g, iB = i0 + g + 8;
    float zA = nvec[((size_t)b * S_ + s0 + iA) * H_ + h] + offh;
    float zB = nvec[((size_t)b * S_ + s0 + iB) * H_ + h] + offh;

    CP_WAIT(0);               // state + v landed
    __syncthreads();

    float dO[4][4];
    float dS[4][4];
    #pragma unroll
    for (int n = 0; n < 4; n++)
        #pragma unroll
        for (int p = 0; p < 4; p++) { dO[n][p] = 0.f; dS[n][p] = 0.f; }

    // Phase 1: out1 = q @ state (own e-tiles); scores = q @ k^T (parity j-tiles)
    #pragma unroll
    for (int kt = 0; kt < 8; kt++) {
        const int d0 = kt * 8;
        uint32_t a0 = qSu[(i0 + g)     * 68 + d0 + tq];
        uint32_t a1 = qSu[(i0 + g + 8) * 68 + d0 + tq];
        uint32_t a2 = qSu[(i0 + g)     * 68 + d0 + tq + 4];
        uint32_t a3 = qSu[(i0 + g + 8) * 68 + d0 + tq + 4];
        #pragma unroll
        for (int nt = 0; nt < 4; nt++) {
            const int e0 = (eh * 4 + nt) * 8;
            uint32_t b0 = stSu[(d0 + tq)     * 68 + e0 + g];   // pre-rounded bits
            uint32_t b1 = stSu[(d0 + tq + 4) * 68 + e0 + g];
            MMA8(dO[nt], a0, a1, a2, a3, b0, b1);
        }
        #pragma unroll
        for (int nt2 = 0; nt2 < 4; nt2++) {
            const int jt = 2 * nt2 + eh;
            if (jt >= ntS) break;
            const int j0 = jt * 8;
            uint32_t b0 = kSu[(j0 + g) * 68 + d0 + tq];
            uint32_t b1 = kSu[(j0 + g) * 68 + d0 + tq + 4];
            MMA8(dS[nt2], a0, a1, a2, a3, b0, b1);
        }
    }

    __syncthreads();           // all reads of stS done; sS may overwrite

    // Causal mask + store parity score tiles
    #pragma unroll
    for (int nt2 = 0; nt2 < 4; nt2++) {
        const int jt = 2 * nt2 + eh;
        if (jt >= ntS) break;
        const int j = jt * 8 + 2 * tq;
        sSu[iA * 65 + j]     = tf32r((j     <= iA) ? dS[nt2][0] : 0.f);
        sSu[iA * 65 + j + 1] = tf32r((j + 1 <= iA) ? dS[nt2][1] : 0.f);
        sSu[iB * 65 + j]     = tf32r((j     <= iB) ? dS[nt2][2] : 0.f);
        sSu[iB * 65 + j + 1] = tf32r((j + 1 <= iB) ? dS[nt2][3] : 0.f);
    }
    __syncthreads();           // scores visible to all

    // Phase 2: out += scores @ v (all causal j-tiles, own e-tiles)
    #pragma unroll
    for (int kt = 0; kt < 8; kt++) {
        if (kt >= ntS) break;
        const int j0 = kt * 8;
        uint32_t a0 = sSu[(i0 + g)     * 65 + j0 + tq];
        uint32_t a1 = sSu[(i0 + g + 8) * 65 + j0 + tq];
        uint32_t a2 = sSu[(i0 + g)     * 65 + j0 + tq + 4];
        uint32_t a3 = sSu[(i0 + g + 8) * 65 + j0 + tq + 4];
        #pragma unroll
        for (int nt = 0; nt < 4; nt++) {
            const int e0 = (eh * 4 + nt) * 8;
            uint32_t b0 = tf32r(vS[(j0 + tq)     * 68 + e0 + g]);
            uint32_t b1 = tf32r(vS[(j0 + tq + 4) * 68 + e0 + g]);
            MMA8(dO[nt], a0, a1, a2, a3, b0, b1);
        }
    }

    // Epilogue: norm scale, stage into oS (aliases qS), coalesced store
    float nA = 1.f / (1.f + __expf(zA));
    float nB = 1.f / (1.f + __expf(zB));
    __syncthreads();           // everyone done reading qS (phase 1)
    #pragma unroll
    for (int nt = 0; nt < 4; nt++) {
        const int e = (eh * 4 + nt) * 8 + 2 * tq;
        oS[iA * 68 + e]     = dO[nt][0] * nA;
        oS[iA * 68 + e + 1] = dO[nt][1] * nA;
        oS[iB * 68 + e]     = dO[nt][2] * nB;
        oS[iB * 68 + e + 1] = dO[nt][3] * nB;
    }
    __syncthreads();

    #pragma unroll
    for (int r = 0; r < 4; r++) {
        int idx = t + r * 256;
        int row = idx >> 4;
        int d4  = (idx & 15) << 2;
        float* op = out + (((size_t)b * S_ + s0 + row) * H_ + h) * D_ + d4;
        *reinterpret_cast<float4*>(op) = *reinterpret_cast<const float4*>(&oS[row * 68 + d4]);
    }
}

// ---------------------------------------------------------------------------
extern "C" void kernel_launch(void* const* d_in, const int* in_sizes, int n_in,
                              void* d_out, int out_size) {
    (void)in_sizes; (void)n_in; (void)out_size;
    const float* qk     = (const float*)d_in[0];
    const float* v      = (const float*)d_in[1];
    const float* nvec   = (const float*)d_in[2];
    const float* offset = (const float*)d_in[3];
    float* out = (float*)d_out;

    const int smem1 = (64 * 68 + 64 * 65 + 64 * 68) * (int)sizeof(float);  // 51456
    const int smem3 = (4 * 64 * 68) * (int)sizeof(float);                  // 69632
    cudaFuncSetAttribute(k_chunk_sum, cudaFuncAttributeMaxDynamicSharedMemorySize, smem1);
    cudaFuncSetAttribute(k_output,    cudaFuncAttributeMaxDynamicSharedMemorySize, smem3);

    k_chunk_sum<<<BH_ * NC_, 256, smem1>>>(qk, v);
    k_prefix<<<128, 256>>>();
    k_output<<<BH_ * NC_, 256, smem3>>>(qk, v, nvec, offset, out);
}